// round 6
// baseline (speedup 1.0000x reference)
#include <cuda_runtime.h>
#include <math.h>

// Problem constants (fixed shapes per reference)
#define Bb 8
#define Cc 256
#define Hf 48
#define Wf 48
#define RR 300
#define PHB 7
#define PWB 7
#define SCALE 0.0625f
#define NBINS (RR * PHB * PWB)   // 14700, divisible by 4
#define MAXW 12                   // max grid points per axis per bin (<= 9 actual)

// Channels-last staged features: [B][H][W][C]  (18.9 MB device scratch)
__device__ float g_featT[(size_t)Bb * Hf * Wf * Cc];

// ---------------------------------------------------------------------------
// Stage 1: transpose [B][C][S] -> [B][S][C],  S = H*W = 2304.
// 32x32 smem tile transpose; S=2304 and C=256 are multiples of 32 (no guards).
// ---------------------------------------------------------------------------
__global__ void __launch_bounds__(1024) transpose_kernel(const float* __restrict__ feat) {
    __shared__ float tile[32][33];
    const int S = Hf * Wf;
    int b  = blockIdx.z;
    int s0 = blockIdx.x * 32;
    int c0 = blockIdx.y * 32;
    int tx = threadIdx.x, ty = threadIdx.y;

    // coalesced read: feat[b][c0+ty][s0+tx]
    tile[ty][tx] = feat[((size_t)b * Cc + (c0 + ty)) * S + (s0 + tx)];
    __syncthreads();
    // coalesced write: featT[b][s0+ty][c0+tx]
    g_featT[((size_t)b * S + (s0 + ty)) * Cc + (c0 + tx)] = tile[tx][ty];
}

// ---------------------------------------------------------------------------
// Exact integral of the unit hat basis centered at g, from -inf to x.
// Matches the reference piecewise form exactly (boundaries give identical
// values after clamping).
// ---------------------------------------------------------------------------
__device__ __forceinline__ float hat_int(float x, float g) {
    float t = x - (g - 1.0f);
    t = fminf(fmaxf(t, 0.0f), 2.0f);
    float lo = 0.5f * t * t;
    float u  = 2.0f - t;
    float hi = 1.0f - 0.5f * u * u;
    return (t <= 1.0f) ? lo : hi;
}

// ---------------------------------------------------------------------------
// Stage 2: one warp per (roi, ph, pw) bin. Lane l handles channels
// {4l..4l+3} and {128+4l..128+4l+3} via two coalesced float4 loads per
// window point. Weights are computed once per bin by 12 lanes into smem.
// ---------------------------------------------------------------------------
__global__ void __launch_bounds__(128) prroi_pool_kernel(
    const float* __restrict__ rois, float* __restrict__ out)
{
    __shared__ float s_wy[4][MAXW];
    __shared__ float s_wx[4][MAXW];

    const int warp = threadIdx.x >> 5;
    const int lane = threadIdx.x & 31;
    const int bin  = blockIdx.x * 4 + warp;     // grid sized exactly: bin < NBINS

    const int r  = bin / (PHB * PWB);
    const int k  = bin % (PHB * PWB);
    const int ph = k / PWB;
    const int pw = k % PWB;

    const float* rp = rois + r * 5;
    const int   b  = (int)rp[0];
    const float x1 = rp[1] * SCALE;
    const float y1 = rp[2] * SCALE;
    const float x2 = rp[3] * SCALE;
    const float y2 = rp[4] * SCALE;

    const float bin_w = fmaxf(x2 - x1, 0.0f) / (float)PWB;
    const float bin_h = fmaxf(y2 - y1, 0.0f) / (float)PHB;

    const float ya = y1 + (float)ph * bin_h;
    const float yb = ya + bin_h;
    const float xa = x1 + (float)pw * bin_w;
    const float xb = xa + bin_w;

    int j_lo = max(0,      (int)ceilf (ya - 1.0f));
    int j_hi = min(Hf - 1, (int)floorf(yb + 1.0f));
    int i_lo = max(0,      (int)ceilf (xa - 1.0f));
    int i_hi = min(Wf - 1, (int)floorf(xb + 1.0f));
    const int nj = j_hi - j_lo + 1;
    const int ni = i_hi - i_lo + 1;

    // Per-bin axis weights (exact hat integrals), computed by 12 lanes.
    if (lane < MAXW) {
        int j = j_lo + lane;
        s_wy[warp][lane] = (j <= j_hi)
            ? (hat_int(yb, (float)j) - hat_int(ya, (float)j)) : 0.0f;
        int i = i_lo + lane;
        s_wx[warp][lane] = (i <= i_hi)
            ? (hat_int(xb, (float)i) - hat_int(xa, (float)i)) : 0.0f;
    }
    __syncwarp();

    const int c0 = lane * 4;                    // channels c0..c0+3 and c0+128..c0+131
    const float* base =
        g_featT + (((size_t)b * Hf + j_lo) * Wf + i_lo) * Cc + c0;

    float4 acc0 = make_float4(0.f, 0.f, 0.f, 0.f);
    float4 acc1 = make_float4(0.f, 0.f, 0.f, 0.f);

    for (int j = 0; j < nj; ++j) {
        const float wy = s_wy[warp][j];
        const float* p = base + (size_t)j * (Wf * Cc);
        for (int i = 0; i < ni; ++i) {
            const float w = wy * s_wx[warp][i];
            float4 f0 = __ldg((const float4*)p);
            float4 f1 = __ldg((const float4*)(p + 128));
            acc0.x += w * f0.x; acc0.y += w * f0.y;
            acc0.z += w * f0.z; acc0.w += w * f0.w;
            acc1.x += w * f1.x; acc1.y += w * f1.y;
            acc1.z += w * f1.z; acc1.w += w * f1.w;
            p += Cc;
        }
    }

    const float area = bin_w * bin_h;
    const float inv  = (area > 0.0f) ? (1.0f / area) : 0.0f;

    // out layout [R][C][7][7]; consecutive channels stride 49.
    size_t o0 = ((size_t)r * Cc + c0) * (PHB * PWB) + k;
    out[o0]                         = acc0.x * inv;
    out[o0 +  1 * (PHB * PWB)]      = acc0.y * inv;
    out[o0 +  2 * (PHB * PWB)]      = acc0.z * inv;
    out[o0 +  3 * (PHB * PWB)]      = acc0.w * inv;
    size_t o1 = o0 + (size_t)128 * (PHB * PWB);
    out[o1]                         = acc1.x * inv;
    out[o1 +  1 * (PHB * PWB)]      = acc1.y * inv;
    out[o1 +  2 * (PHB * PWB)]      = acc1.z * inv;
    out[o1 +  3 * (PHB * PWB)]      = acc1.w * inv;
}

// ---------------------------------------------------------------------------
// Harness entry
// ---------------------------------------------------------------------------
extern "C" void kernel_launch(void* const* d_in, const int* in_sizes, int n_in,
                              void* d_out, int out_size) {
    const float* features = (const float*)d_in[0];   // [8,256,48,48]
    const float* rois     = (const float*)d_in[1];   // [300,5]
    float*       out      = (float*)d_out;           // [300,256,7,7]
    (void)in_sizes; (void)n_in; (void)out_size;

    dim3 tgrid((Hf * Wf) / 32, Cc / 32, Bb);         // (72, 8, 8)
    transpose_kernel<<<tgrid, dim3(32, 32)>>>(features);

    prroi_pool_kernel<<<NBINS / 4, 128>>>(rois, out);
}